// round 3
// baseline (speedup 1.0000x reference)
#include <cuda_runtime.h>

#define B_   4
#define S_   2048
#define H_   16
#define DK_  64
#define DM_  1024
#define M_   (B_*S_)          // 8192

// Scratch (allocation-free rule: __device__ globals)
__device__ float g_q[(size_t)B_*H_*S_*DK_];    // [b,h,s,d]
__device__ float g_k[(size_t)B_*H_*S_*DK_];
__device__ float g_v[(size_t)B_*H_*S_*DK_];
__device__ float g_ctx[(size_t)M_*DM_];        // [b,s, h*d] merged heads

// ---------------------------------------------------------------------------
// C[M,N] = A[M,K] * W[N,K]^T + bias[N]     (torch Linear semantics)
// Tiles: 64x64 output, K-tile 32. 256 threads, 4x4 register tile per thread.
// Smem stored k-major (transposed) with pad 68 -> conflict-free LDS.128 reads.
// SPLIT=true writes output in head-split layout [b,h,s,d].
// ---------------------------------------------------------------------------
template<bool SPLIT>
__global__ __launch_bounds__(256)
void gemm_nt_kernel(const float* __restrict__ A,
                    const float* __restrict__ W,
                    const float* __restrict__ bias,
                    float* __restrict__ C)
{
    __shared__ float At[32*68];
    __shared__ float Bt[32*68];

    const int tid = threadIdx.x;
    const int tx  = tid & 15;
    const int ty  = tid >> 4;
    const int m0  = blockIdx.x * 64;
    const int n0  = blockIdx.y * 64;

    const int lrow = tid >> 2;          // 0..63
    const int lk4  = (tid & 3) << 2;    // 0,4,8,12

    const float* Ap = A + (size_t)(m0 + lrow) * DM_ + lk4;
    const float* Wp = W + (size_t)(n0 + lrow) * DM_ + lk4;

    float acc[4][4] = {};

    for (int k0 = 0; k0 < DM_; k0 += 32) {
        #pragma unroll
        for (int rep = 0; rep < 2; rep++) {
            float4 av = *(const float4*)(Ap + k0 + rep*16);
            float4 bv = *(const float4*)(Wp + k0 + rep*16);
            int kk = lk4 + rep*16;
            At[(kk+0)*68 + lrow] = av.x;
            At[(kk+1)*68 + lrow] = av.y;
            At[(kk+2)*68 + lrow] = av.z;
            At[(kk+3)*68 + lrow] = av.w;
            Bt[(kk+0)*68 + lrow] = bv.x;
            Bt[(kk+1)*68 + lrow] = bv.y;
            Bt[(kk+2)*68 + lrow] = bv.z;
            Bt[(kk+3)*68 + lrow] = bv.w;
        }
        __syncthreads();

        #pragma unroll 8
        for (int kk = 0; kk < 32; kk++) {
            float4 a4 = *(const float4*)&At[kk*68 + ty*4];
            float4 b4 = *(const float4*)&Bt[kk*68 + tx*4];
            float ar[4] = {a4.x, a4.y, a4.z, a4.w};
            float br[4] = {b4.x, b4.y, b4.z, b4.w};
            #pragma unroll
            for (int r = 0; r < 4; r++)
                #pragma unroll
                for (int c = 0; c < 4; c++)
                    acc[r][c] = fmaf(ar[r], br[c], acc[r][c]);
        }
        __syncthreads();
    }

    const int ncol = n0 + tx*4;
    const float4 bb = *(const float4*)(bias + ncol);
    #pragma unroll
    for (int r = 0; r < 4; r++) {
        const int m = m0 + ty*4 + r;
        float4 o;
        o.x = acc[r][0] + bb.x;
        o.y = acc[r][1] + bb.y;
        o.z = acc[r][2] + bb.z;
        o.w = acc[r][3] + bb.w;
        if (SPLIT) {
            const int b = m >> 11;          // /S_
            const int s = m & (S_-1);
            const int h = ncol >> 6;        // /DK_
            const int d = ncol & 63;
            *(float4*)(C + ((size_t)((b*H_ + h)*S_ + s))*DK_ + d) = o;
        } else {
            *(float4*)(C + (size_t)m*DM_ + ncol) = o;
        }
    }
}

// ---------------------------------------------------------------------------
// Fused flash attention: one block per (b*h, 64-query-tile).
// Online softmax; row reductions via half-warp shuffle butterflies
// (tx = lane%16, so each row group lives in one 16-lane half-warp).
// Dynamic smem: Qt,Kt (d-major, [64][68]) + Vs,Ps (j-major, [64][68]).
// ---------------------------------------------------------------------------
#define ATTN_SMEM (4 * 64 * 68 * (int)sizeof(float))   // 69632 B

__global__ __launch_bounds__(256)
void attn_kernel()
{
    extern __shared__ float sm[];
    float* Qt = sm;              // Qt[d*68 + i]   (pre-scaled by 1/8)
    float* Kt = sm + 64*68;      // Kt[d*68 + j]
    float* Vs = sm + 2*64*68;    // Vs[j*68 + d]
    float* Ps = sm + 3*64*68;    // Ps[j*68 + i]

    const int tid = threadIdx.x;
    const int tx  = tid & 15;
    const int ty  = tid >> 4;
    const int q0  = blockIdx.x * 64;
    const int bh  = blockIdx.y;

    const float* qp = g_q + (size_t)bh * S_ * DK_;
    const float* kp = g_k + (size_t)bh * S_ * DK_;
    const float* vp = g_v + (size_t)bh * S_ * DK_;

    const int lr  = tid >> 2;        // 0..63
    const int ld4 = (tid & 3) << 2;  // 0,4,8,12

    // Load Q tile (transposed, scaled by 1/sqrt(d_k)=0.125)
    #pragma unroll
    for (int rep = 0; rep < 4; rep++) {
        const int dd = ld4 + rep*16;
        float4 v = *(const float4*)(qp + (size_t)(q0 + lr)*DK_ + dd);
        Qt[(dd+0)*68 + lr] = v.x * 0.125f;
        Qt[(dd+1)*68 + lr] = v.y * 0.125f;
        Qt[(dd+2)*68 + lr] = v.z * 0.125f;
        Qt[(dd+3)*68 + lr] = v.w * 0.125f;
    }

    float m_run[4], l_run[4], o[4][4];
    #pragma unroll
    for (int r = 0; r < 4; r++) {
        m_run[r] = -1e30f;
        l_run[r] = 0.f;
        #pragma unroll
        for (int c = 0; c < 4; c++) o[r][c] = 0.f;
    }

    for (int j0 = 0; j0 < S_; j0 += 64) {
        // Load K (transposed) + V (row-major) tiles
        #pragma unroll
        for (int rep = 0; rep < 4; rep++) {
            const int dd = ld4 + rep*16;
            float4 kv = *(const float4*)(kp + (size_t)(j0 + lr)*DK_ + dd);
            float4 vv = *(const float4*)(vp + (size_t)(j0 + lr)*DK_ + dd);
            Kt[(dd+0)*68 + lr] = kv.x;
            Kt[(dd+1)*68 + lr] = kv.y;
            Kt[(dd+2)*68 + lr] = kv.z;
            Kt[(dd+3)*68 + lr] = kv.w;
            *(float4*)&Vs[lr*68 + dd] = vv;
        }
        __syncthreads();

        // S = Q K^T (scaled): 4x4 per thread
        float s[4][4] = {};
        #pragma unroll 8
        for (int d = 0; d < 64; d++) {
            float4 a4 = *(const float4*)&Qt[d*68 + ty*4];
            float4 b4 = *(const float4*)&Kt[d*68 + tx*4];
            float ar[4] = {a4.x, a4.y, a4.z, a4.w};
            float br[4] = {b4.x, b4.y, b4.z, b4.w};
            #pragma unroll
            for (int r = 0; r < 4; r++)
                #pragma unroll
                for (int c = 0; c < 4; c++)
                    s[r][c] = fmaf(ar[r], br[c], s[r][c]);
        }

        // Online softmax per row (reduction across tx via half-warp shuffle)
        #pragma unroll
        for (int r = 0; r < 4; r++) {
            float pm = fmaxf(fmaxf(s[r][0], s[r][1]), fmaxf(s[r][2], s[r][3]));
            #pragma unroll
            for (int off = 1; off < 16; off <<= 1)
                pm = fmaxf(pm, __shfl_xor_sync(0xffffffffu, pm, off));
            const float mnew  = fmaxf(m_run[r], pm);
            const float alpha = __expf(m_run[r] - mnew);
            float sum = 0.f;
            #pragma unroll
            for (int c = 0; c < 4; c++) {
                const float p = __expf(s[r][c] - mnew);
                s[r][c] = p;
                sum += p;
            }
            #pragma unroll
            for (int off = 1; off < 16; off <<= 1)
                sum += __shfl_xor_sync(0xffffffffu, sum, off);
            l_run[r] = l_run[r]*alpha + sum;
            m_run[r] = mnew;
            #pragma unroll
            for (int c = 0; c < 4; c++) o[r][c] *= alpha;
        }

        // Stage P (transposed: Ps[j][i]) for the PV gemm
        #pragma unroll
        for (int c = 0; c < 4; c++)
            #pragma unroll
            for (int r = 0; r < 4; r++)
                Ps[(tx*4 + c)*68 + ty*4 + r] = s[r][c];
        __syncthreads();

        // O += P @ V
        #pragma unroll 8
        for (int j = 0; j < 64; j++) {
            float4 p4 = *(const float4*)&Ps[j*68 + ty*4];
            float4 v4 = *(const float4*)&Vs[j*68 + tx*4];
            float pr[4] = {p4.x, p4.y, p4.z, p4.w};
            float vr[4] = {v4.x, v4.y, v4.z, v4.w};
            #pragma unroll
            for (int r = 0; r < 4; r++)
                #pragma unroll
                for (int c = 0; c < 4; c++)
                    o[r][c] = fmaf(pr[r], vr[c], o[r][c]);
        }
        __syncthreads();
    }

    // Normalize and write context in merged-head layout [b, s, h*64 + d]
    const int b = bh >> 4;
    const int h = bh & 15;
    #pragma unroll
    for (int r = 0; r < 4; r++) {
        const float inv = 1.f / l_run[r];
        float4 ov = { o[r][0]*inv, o[r][1]*inv, o[r][2]*inv, o[r][3]*inv };
        const size_t idx = ((size_t)(b*S_ + q0 + ty*4 + r))*DM_ + h*DK_ + tx*4;
        *(float4*)(g_ctx + idx) = ov;
    }
}

// ---------------------------------------------------------------------------
extern "C" void kernel_launch(void* const* d_in, const int* in_sizes, int n_in,
                              void* d_out, int out_size)
{
    (void)in_sizes; (void)n_in; (void)out_size;
    const float* query = (const float*)d_in[0];
    const float* key   = (const float*)d_in[1];
    const float* value = (const float*)d_in[2];
    const float* Wq    = (const float*)d_in[3];
    const float* bq    = (const float*)d_in[4];
    const float* Wk    = (const float*)d_in[5];
    const float* bk    = (const float*)d_in[6];
    const float* Wv    = (const float*)d_in[7];
    const float* bv    = (const float*)d_in[8];
    const float* Wo    = (const float*)d_in[9];
    const float* bo    = (const float*)d_in[10];
    float* out = (float*)d_out;

    float *pq, *pk, *pv, *pctx;
    cudaGetSymbolAddress((void**)&pq,   g_q);
    cudaGetSymbolAddress((void**)&pk,   g_k);
    cudaGetSymbolAddress((void**)&pv,   g_v);
    cudaGetSymbolAddress((void**)&pctx, g_ctx);

    const dim3 gproj(M_/64, DM_/64);   // 128 x 16
    gemm_nt_kernel<true><<<gproj, 256>>>(query, Wq, bq, pq);
    gemm_nt_kernel<true><<<gproj, 256>>>(key,   Wk, bk, pk);
    gemm_nt_kernel<true><<<gproj, 256>>>(value, Wv, bv, pv);

    cudaFuncSetAttribute(attn_kernel,
                         cudaFuncAttributeMaxDynamicSharedMemorySize, ATTN_SMEM);
    attn_kernel<<<dim3(S_/64, B_*H_), 256, ATTN_SMEM>>>();

    gemm_nt_kernel<false><<<gproj, 256>>>(pctx, Wo, bo, out);
}

// round 5
// speedup vs baseline: 2.6231x; 2.6231x over previous
#include <cuda_runtime.h>
#include <cuda_bf16.h>
#include <cstdint>

#define B_   4
#define S_   2048
#define H_   16
#define DK_  64
#define DM_  1024
#define M_   (B_*S_)          // 8192

// Scratch (allocation-free rule: __device__ globals)
__device__ float g_q[(size_t)B_*H_*S_*DK_];    // [b,h,s,d]
__device__ float g_k[(size_t)B_*H_*S_*DK_];
__device__ float g_v[(size_t)B_*H_*S_*DK_];
__device__ float g_ctx[(size_t)M_*DM_];        // [b,s,h*d]

// ===========================================================================
// Helpers: mma.sync / ldmatrix (portable PTX, legal on base sm_103 target)
// ===========================================================================
__device__ __forceinline__ uint32_t smem_u32(const void* p) {
    uint32_t a;
    asm("{ .reg .u64 t; cvta.to.shared.u64 t, %1; cvt.u32.u64 %0, t; }"
        : "=r"(a) : "l"(p));
    return a;
}

__device__ __forceinline__ void ldsm_x4(uint32_t& r0, uint32_t& r1,
                                        uint32_t& r2, uint32_t& r3, uint32_t a) {
    asm volatile("ldmatrix.sync.aligned.m8n8.x4.shared.b16 {%0,%1,%2,%3}, [%4];"
                 : "=r"(r0), "=r"(r1), "=r"(r2), "=r"(r3) : "r"(a));
}
__device__ __forceinline__ void ldsm_x2(uint32_t& r0, uint32_t& r1, uint32_t a) {
    asm volatile("ldmatrix.sync.aligned.m8n8.x2.shared.b16 {%0,%1}, [%2];"
                 : "=r"(r0), "=r"(r1) : "r"(a));
}
__device__ __forceinline__ void ldsm_x2t(uint32_t& r0, uint32_t& r1, uint32_t a) {
    asm volatile("ldmatrix.sync.aligned.m8n8.x2.trans.shared.b16 {%0,%1}, [%2];"
                 : "=r"(r0), "=r"(r1) : "r"(a));
}
__device__ __forceinline__ void mma_bf16(float* c,
                                         uint32_t a0, uint32_t a1, uint32_t a2, uint32_t a3,
                                         uint32_t b0, uint32_t b1) {
    asm volatile("mma.sync.aligned.m16n8k16.row.col.f32.bf16.bf16.f32 "
                 "{%0,%1,%2,%3}, {%4,%5,%6,%7}, {%8,%9}, {%0,%1,%2,%3};"
                 : "+f"(c[0]), "+f"(c[1]), "+f"(c[2]), "+f"(c[3])
                 : "r"(a0), "r"(a1), "r"(a2), "r"(a3), "r"(b0), "r"(b1));
}

#define STS64(addr, r0, r1) \
    asm volatile("st.shared.v2.b32 [%0], {%1,%2};" \
                 :: "r"(addr), "r"(r0), "r"(r1) : "memory")

__device__ __forceinline__ uint32_t pack_bf16(float x, float y) {
    __nv_bfloat162 t = __floats2bfloat162_rn(x, y);   // .x = low half
    return reinterpret_cast<uint32_t&>(t);
}
// fp32 -> bf16 hi/lo split (pairwise, packed)
__device__ __forceinline__ void split2(float x, float y, uint32_t& hi, uint32_t& lo) {
    __nv_bfloat16 hx = __float2bfloat16(x);
    __nv_bfloat16 hy = __float2bfloat16(y);
    __nv_bfloat162 h; h.x = hx; h.y = hy;
    hi = reinterpret_cast<uint32_t&>(h);
    lo = pack_bf16(x - __bfloat162float(hx), y - __bfloat162float(hy));
}
__device__ __forceinline__ void split_sts(uint32_t addr_hi, uint32_t addr_lo, float4 v) {
    uint32_t h0, l0, h1, l1;
    split2(v.x, v.y, h0, l0);
    split2(v.z, v.w, h1, l1);
    STS64(addr_hi, h0, h1);
    STS64(addr_lo, l0, l1);
}

// ===========================================================================
// GEMM: C[M,N] = A[M,K] * W[N,K]^T + bias[N]   (3-term bf16 compensated mma)
// CTA 128x128, 8 warps (4m x 2n), warp tile 32x64, K-tile 32, double buffer.
// Planes per stage: Ah, Al, Bh, Bl; bf16 rows padded to 40 elems (80B).
// ===========================================================================
#define G_RS    40            // bf16 elems per row (80 B, LDSM conflict-free)
#define G_PL    (128*80)      // 10240 B per plane
#define G_STAGE (4*G_PL)      // 40960 B
#define G_SMEM  (2*G_STAGE)   // 81920 B
#define G_AH 0
#define G_AL G_PL
#define G_BH (2*G_PL)
#define G_BL (3*G_PL)
#define NKT_ (DM_/32)         // 32 k-tiles

__device__ __forceinline__ void g_load(const float* __restrict__ A,
                                       const float* __restrict__ W,
                                       int m0, int n0, int k0, int tid,
                                       float4* pa, float4* pb) {
    #pragma unroll
    for (int i = 0; i < 4; i++) {
        const int u = tid + i*256;          // 0..1023
        const int row = u >> 3, c4 = u & 7; // 8 float4 per 32-elem row
        pa[i] = __ldg((const float4*)(A + (size_t)(m0+row)*DM_ + k0 + c4*4));
        pb[i] = __ldg((const float4*)(W + (size_t)(n0+row)*DM_ + k0 + c4*4));
    }
}
__device__ __forceinline__ void g_sts(uint32_t buf, int tid,
                                      const float4* pa, const float4* pb) {
    #pragma unroll
    for (int i = 0; i < 4; i++) {
        const int u = tid + i*256;
        const int row = u >> 3, c4 = u & 7;
        const uint32_t off = (uint32_t)(row*80 + c4*8);
        split_sts(buf + G_AH + off, buf + G_AL + off, pa[i]);
        split_sts(buf + G_BH + off, buf + G_BL + off, pb[i]);
    }
}

template<bool SPLIT>
__global__ __launch_bounds__(256)
void gemm_mma_kernel(const float* __restrict__ A,
                     const float* __restrict__ W,
                     const float* __restrict__ bias,
                     float* __restrict__ C)
{
    extern __shared__ char smem[];
    const uint32_t sb = smem_u32(smem);
    const int tid = threadIdx.x;
    const int w = tid >> 5, l = tid & 31;
    const int wm = w & 3, wn = w >> 2;          // warp grid 4m x 2n
    const int m0 = blockIdx.x * 128;
    const int n0 = blockIdx.y * 128;

    float acc[2][8][4];
    #pragma unroll
    for (int mt = 0; mt < 2; mt++)
        #pragma unroll
        for (int nt = 0; nt < 8; nt++)
            #pragma unroll
            for (int r = 0; r < 4; r++) acc[mt][nt][r] = 0.f;

    float4 pa[4], pb[4];
    g_load(A, W, m0, n0, 0, tid, pa, pb);
    g_sts(sb, tid, pa, pb);
    __syncthreads();

    // ldmatrix source addresses (per-thread row/col pattern)
    const uint32_t a_row = (uint32_t)(wm*32 + (l & 15));
    const uint32_t a_kof = (uint32_t)(8 * (l >> 4));
    const uint32_t b_row = (uint32_t)(wn*64 + (l & 7));
    const uint32_t b_kof = (uint32_t)(8 * ((l >> 3) & 1));

    for (int kt = 0; kt < NKT_; kt++) {
        const uint32_t buf = sb + (uint32_t)((kt & 1) * G_STAGE);
        if (kt + 1 < NKT_)
            g_load(A, W, m0, n0, (kt+1)*32, tid, pa, pb);

        #pragma unroll
        for (int ks = 0; ks < 2; ks++) {
            uint32_t ah[2][4], al[2][4];
            #pragma unroll
            for (int mt = 0; mt < 2; mt++) {
                const uint32_t ao = (a_row + mt*16)*80 + (ks*16 + a_kof)*2;
                ldsm_x4(ah[mt][0], ah[mt][1], ah[mt][2], ah[mt][3], buf + G_AH + ao);
                ldsm_x4(al[mt][0], al[mt][1], al[mt][2], al[mt][3], buf + G_AL + ao);
            }
            #pragma unroll
            for (int nt = 0; nt < 8; nt++) {
                const uint32_t bo = (b_row + nt*8)*80 + (ks*16 + b_kof)*2;
                uint32_t bh0, bh1, bl0, bl1;
                ldsm_x2(bh0, bh1, buf + G_BH + bo);
                ldsm_x2(bl0, bl1, buf + G_BL + bo);
                #pragma unroll
                for (int mt = 0; mt < 2; mt++) {
                    mma_bf16(acc[mt][nt], ah[mt][0], ah[mt][1], ah[mt][2], ah[mt][3], bh0, bh1);
                    mma_bf16(acc[mt][nt], ah[mt][0], ah[mt][1], ah[mt][2], ah[mt][3], bl0, bl1);
                    mma_bf16(acc[mt][nt], al[mt][0], al[mt][1], al[mt][2], al[mt][3], bh0, bh1);
                }
            }
        }
        if (kt + 1 < NKT_) {
            const uint32_t nbuf = sb + (uint32_t)(((kt+1) & 1) * G_STAGE);
            g_sts(nbuf, tid, pa, pb);
        }
        __syncthreads();
    }

    // Epilogue
    #pragma unroll
    for (int mt = 0; mt < 2; mt++) {
        const int mrow = m0 + wm*32 + mt*16 + (l >> 2);
        #pragma unroll
        for (int nt = 0; nt < 8; nt++) {
            const int ncol = n0 + wn*64 + nt*8 + (l & 3)*2;
            const float2 bb = *(const float2*)(bias + ncol);
            float2 o0 = { acc[mt][nt][0] + bb.x, acc[mt][nt][1] + bb.y };
            float2 o1 = { acc[mt][nt][2] + bb.x, acc[mt][nt][3] + bb.y };
            if (SPLIT) {
                const int h = ncol >> 6, d = ncol & 63;
                const int b0i = mrow >> 11, s0i = mrow & (S_-1);
                *(float2*)(C + ((size_t)((b0i*H_ + h)*S_ + s0i))*DK_ + d) = o0;
                const int m2 = mrow + 8;
                const int b1i = m2 >> 11, s1i = m2 & (S_-1);
                *(float2*)(C + ((size_t)((b1i*H_ + h)*S_ + s1i))*DK_ + d) = o1;
            } else {
                *(float2*)(C + (size_t)mrow*DM_ + ncol) = o0;
                *(float2*)(C + (size_t)(mrow+8)*DM_ + ncol) = o1;
            }
        }
    }
}

// ===========================================================================
// Flash attention via mma.sync: 128-query tile, 8 warps x 16 rows.
// Q resident in registers (hi/lo frags); K,V staged per 64-key block as
// bf16 hi/lo planes (row stride 72 bf16 = 144 B, LDSM conflict-free).
// P converted to A-fragments in-register (no smem round trip).
// ===========================================================================
#define AT_RS 72              // bf16 elems per row
#define AT_PL (64*144)        // 9216 B per plane
#define AT_KH 0
#define AT_KL AT_PL
#define AT_VH (2*AT_PL)
#define AT_VL (3*AT_PL)
#define ATTN_SMEM (4*AT_PL)   // 36864 B

__global__ __launch_bounds__(256)
void attn_mma_kernel()
{
    extern __shared__ char smem[];
    const uint32_t sb = smem_u32(smem);
    const int tid = threadIdx.x;
    const int w = tid >> 5, l = tid & 31;
    const int q0 = blockIdx.x * 128;
    const int bh = blockIdx.y;

    const float* qp = g_q + (size_t)bh * S_ * DK_;
    const float* kp = g_k + (size_t)bh * S_ * DK_;
    const float* vp = g_v + (size_t)bh * S_ * DK_;

    // Q fragments (scaled by 1/sqrt(64)=0.125), hi/lo, all 4 k16-steps
    uint32_t qh[4][4], ql[4][4];
    {
        const int r1 = q0 + w*16 + (l >> 2);
        #pragma unroll
        for (int ks = 0; ks < 4; ks++) {
            #pragma unroll
            for (int rg = 0; rg < 4; rg++) {
                const int row = r1 + ((rg & 1) ? 8 : 0);
                const int col = ks*16 + (l & 3)*2 + ((rg & 2) ? 8 : 0);
                const float2 v = *(const float2*)(qp + (size_t)row*DK_ + col);
                split2(v.x * 0.125f, v.y * 0.125f, qh[ks][rg], ql[ks][rg]);
            }
        }
    }

    float o[8][4];
    #pragma unroll
    for (int t = 0; t < 8; t++)
        #pragma unroll
        for (int r = 0; r < 4; r++) o[t][r] = 0.f;
    float m1 = -1e30f, m2 = -1e30f, l1 = 0.f, l2 = 0.f;

    // ldmatrix address patterns
    const uint32_t kb_row = (uint32_t)(l & 7);
    const uint32_t kb_kof = (uint32_t)(8 * ((l >> 3) & 1));

    for (int j0 = 0; j0 < S_; j0 += 64) {
        __syncthreads();   // previous block's LDSM reads done
        // stage K,V (64x64 fp32 each) as bf16 hi/lo planes
        #pragma unroll
        for (int i = 0; i < 4; i++) {
            const int u = tid + i*256;           // 0..1023
            const int row = u >> 4, c4 = u & 15; // 16 float4 per 64-elem row
            const uint32_t off = (uint32_t)(row*144 + c4*8);
            const float4 kv = __ldg((const float4*)(kp + (size_t)(j0+row)*DK_ + c4*4));
            split_sts(sb + AT_KH + off, sb + AT_KL + off, kv);
            const float4 vv = __ldg((const float4*)(vp + (size_t)(j0+row)*DK_ + c4*4));
            split_sts(sb + AT_VH + off, sb + AT_VL + off, vv);
        }
        __syncthreads();

        // S = Q K^T  (8 n-tiles of 8 keys each)
        float s[8][4];
        #pragma unroll
        for (int t = 0; t < 8; t++)
            #pragma unroll
            for (int r = 0; r < 4; r++) s[t][r] = 0.f;

        #pragma unroll
        for (int ks = 0; ks < 4; ks++) {
            #pragma unroll
            for (int t = 0; t < 8; t++) {
                const uint32_t bo = (uint32_t)((t*8 + kb_row)*144 + (ks*16 + kb_kof)*2);
                uint32_t bh0, bh1, bl0, bl1;
                ldsm_x2(bh0, bh1, sb + AT_KH + bo);
                ldsm_x2(bl0, bl1, sb + AT_KL + bo);
                mma_bf16(s[t], qh[ks][0], qh[ks][1], qh[ks][2], qh[ks][3], bh0, bh1);
                mma_bf16(s[t], qh[ks][0], qh[ks][1], qh[ks][2], qh[ks][3], bl0, bl1);
                mma_bf16(s[t], ql[ks][0], ql[ks][1], ql[ks][2], ql[ks][3], bh0, bh1);
            }
        }

        // Online softmax (rows r1 = regs 0,1 ; r2 = regs 2,3)
        float rm1 = -1e30f, rm2 = -1e30f;
        #pragma unroll
        for (int t = 0; t < 8; t++) {
            rm1 = fmaxf(rm1, fmaxf(s[t][0], s[t][1]));
            rm2 = fmaxf(rm2, fmaxf(s[t][2], s[t][3]));
        }
        rm1 = fmaxf(rm1, __shfl_xor_sync(0xffffffffu, rm1, 1));
        rm1 = fmaxf(rm1, __shfl_xor_sync(0xffffffffu, rm1, 2));
        rm2 = fmaxf(rm2, __shfl_xor_sync(0xffffffffu, rm2, 1));
        rm2 = fmaxf(rm2, __shfl_xor_sync(0xffffffffu, rm2, 2));

        const float mn1 = fmaxf(m1, rm1), mn2 = fmaxf(m2, rm2);
        const float al1 = __expf(m1 - mn1), al2 = __expf(m2 - mn2);
        float sum1 = 0.f, sum2 = 0.f;
        #pragma unroll
        for (int t = 0; t < 8; t++) {
            s[t][0] = __expf(s[t][0] - mn1);
            s[t][1] = __expf(s[t][1] - mn1);
            s[t][2] = __expf(s[t][2] - mn2);
            s[t][3] = __expf(s[t][3] - mn2);
            sum1 += s[t][0] + s[t][1];
            sum2 += s[t][2] + s[t][3];
        }
        sum1 += __shfl_xor_sync(0xffffffffu, sum1, 1);
        sum1 += __shfl_xor_sync(0xffffffffu, sum1, 2);
        sum2 += __shfl_xor_sync(0xffffffffu, sum2, 1);
        sum2 += __shfl_xor_sync(0xffffffffu, sum2, 2);
        l1 = l1*al1 + sum1; l2 = l2*al2 + sum2;
        m1 = mn1; m2 = mn2;
        #pragma unroll
        for (int t = 0; t < 8; t++) {
            o[t][0] *= al1; o[t][1] *= al1;
            o[t][2] *= al2; o[t][3] *= al2;
        }

        // O += P @ V   (P -> A-frags in-register; V via ldmatrix.trans)
        #pragma unroll
        for (int ks = 0; ks < 4; ks++) {
            uint32_t ph[4], pl[4];
            split2(s[2*ks  ][0], s[2*ks  ][1], ph[0], pl[0]);
            split2(s[2*ks  ][2], s[2*ks  ][3], ph[1], pl[1]);
            split2(s[2*ks+1][0], s[2*ks+1][1], ph[2], pl[2]);
            split2(s[2*ks+1][2], s[2*ks+1][3], ph[3], pl[3]);
            const uint32_t vrow = (uint32_t)(ks*16 + (l & 7) + 8*((l >> 3) & 1));
            #pragma unroll
            for (int nt = 0; nt < 8; nt++) {
                const uint32_t vo = vrow*144 + (uint32_t)(nt*8)*2;
                uint32_t vh0, vh1, vl0, vl1;
                ldsm_x2t(vh0, vh1, sb + AT_VH + vo);
                ldsm_x2t(vl0, vl1, sb + AT_VL + vo);
                mma_bf16(o[nt], ph[0], ph[1], ph[2], ph[3], vh0, vh1);
                mma_bf16(o[nt], ph[0], ph[1], ph[2], ph[3], vl0, vl1);
                mma_bf16(o[nt], pl[0], pl[1], pl[2], pl[3], vh0, vh1);
            }
        }
    }

    // Normalize + store to merged-head ctx [b, s, h*64+d]
    const float i1 = 1.f / l1, i2 = 1.f / l2;
    const int b = bh >> 4, h = bh & 15;
    const int row1 = q0 + w*16 + (l >> 2);
    #pragma unroll
    for (int t = 0; t < 8; t++) {
        const int col = h*DK_ + t*8 + (l & 3)*2;
        float2 o0 = { o[t][0]*i1, o[t][1]*i1 };
        float2 o1 = { o[t][2]*i2, o[t][3]*i2 };
        *(float2*)(g_ctx + (size_t)(b*S_ + row1    )*DM_ + col) = o0;
        *(float2*)(g_ctx + (size_t)(b*S_ + row1 + 8)*DM_ + col) = o1;
    }
}

// ===========================================================================
extern "C" void kernel_launch(void* const* d_in, const int* in_sizes, int n_in,
                              void* d_out, int out_size)
{
    (void)in_sizes; (void)n_in; (void)out_size;
    const float* query = (const float*)d_in[0];
    const float* key   = (const float*)d_in[1];
    const float* value = (const float*)d_in[2];
    const float* Wq    = (const float*)d_in[3];
    const float* bq    = (const float*)d_in[4];
    const float* Wk    = (const float*)d_in[5];
    const float* bk    = (const float*)d_in[6];
    const float* Wv    = (const float*)d_in[7];
    const float* bv    = (const float*)d_in[8];
    const float* Wo    = (const float*)d_in[9];
    const float* bo    = (const float*)d_in[10];
    float* out = (float*)d_out;

    float *pq, *pk, *pv, *pctx;
    cudaGetSymbolAddress((void**)&pq,   g_q);
    cudaGetSymbolAddress((void**)&pk,   g_k);
    cudaGetSymbolAddress((void**)&pv,   g_v);
    cudaGetSymbolAddress((void**)&pctx, g_ctx);

    cudaFuncSetAttribute(gemm_mma_kernel<true>,
                         cudaFuncAttributeMaxDynamicSharedMemorySize, G_SMEM);
    cudaFuncSetAttribute(gemm_mma_kernel<false>,
                         cudaFuncAttributeMaxDynamicSharedMemorySize, G_SMEM);

    const dim3 gproj(M_/128, DM_/128);   // 64 x 8
    gemm_mma_kernel<true><<<gproj, 256, G_SMEM>>>(query, Wq, bq, pq);
    gemm_mma_kernel<true><<<gproj, 256, G_SMEM>>>(key,   Wk, bk, pk);
    gemm_mma_kernel<true><<<gproj, 256, G_SMEM>>>(value, Wv, bv, pv);

    attn_mma_kernel<<<dim3(S_/128, B_*H_), 256, ATTN_SMEM>>>();

    gemm_mma_kernel<false><<<gproj, 256, G_SMEM>>>(pctx, Wo, bo, out);
}

// round 6
// speedup vs baseline: 2.8403x; 1.0828x over previous
#include <cuda_runtime.h>
#include <cuda_bf16.h>
#include <cstdint>

#define B_   4
#define S_   2048
#define H_   16
#define DK_  64
#define DM_  1024
#define M_   (B_*S_)          // 8192
#define NA_  ((size_t)M_*DM_) // 8M elems
#define NW_  ((size_t)DM_*DM_)// 1M elems

// ---------------- scratch (__device__ globals; no allocs) ------------------
// bf16 hi/lo planes of the fp32 inputs (A operands of QKV projections)
__device__ __nv_bfloat16 g_xqh[NA_], g_xql[NA_];
__device__ __nv_bfloat16 g_xkh[NA_], g_xkl[NA_];
__device__ __nv_bfloat16 g_xvh[NA_], g_xvl[NA_];
// weights
__device__ __nv_bfloat16 g_wqh[NW_], g_wql[NW_];
__device__ __nv_bfloat16 g_wkh[NW_], g_wkl[NW_];
__device__ __nv_bfloat16 g_wvh[NW_], g_wvl[NW_];
__device__ __nv_bfloat16 g_woh[NW_], g_wol[NW_];
// head-split projections [b,h,s,d], bf16 hi/lo (Q pre-scaled by 0.125)
__device__ __nv_bfloat16 g_qh[NA_], g_ql[NA_];
__device__ __nv_bfloat16 g_kh[NA_], g_kl[NA_];
__device__ __nv_bfloat16 g_vh[NA_], g_vl[NA_];
// merged-head context [b,s,h*d], bf16 hi/lo
__device__ __nv_bfloat16 g_ch[NA_], g_cl[NA_];

// ---------------- PTX helpers ----------------------------------------------
__device__ __forceinline__ uint32_t smem_u32(const void* p) {
    uint32_t a;
    asm("{ .reg .u64 t; cvta.to.shared.u64 t, %1; cvt.u32.u64 %0, t; }"
        : "=r"(a) : "l"(p));
    return a;
}
__device__ __forceinline__ void ldsm_x4(uint32_t& r0, uint32_t& r1,
                                        uint32_t& r2, uint32_t& r3, uint32_t a) {
    asm volatile("ldmatrix.sync.aligned.m8n8.x4.shared.b16 {%0,%1,%2,%3}, [%4];"
                 : "=r"(r0), "=r"(r1), "=r"(r2), "=r"(r3) : "r"(a));
}
__device__ __forceinline__ void ldsm_x2(uint32_t& r0, uint32_t& r1, uint32_t a) {
    asm volatile("ldmatrix.sync.aligned.m8n8.x2.shared.b16 {%0,%1}, [%2];"
                 : "=r"(r0), "=r"(r1) : "r"(a));
}
__device__ __forceinline__ void ldsm_x2t(uint32_t& r0, uint32_t& r1, uint32_t a) {
    asm volatile("ldmatrix.sync.aligned.m8n8.x2.trans.shared.b16 {%0,%1}, [%2];"
                 : "=r"(r0), "=r"(r1) : "r"(a));
}
__device__ __forceinline__ void mma_bf16(float* c,
                                         uint32_t a0, uint32_t a1, uint32_t a2, uint32_t a3,
                                         uint32_t b0, uint32_t b1) {
    asm volatile("mma.sync.aligned.m16n8k16.row.col.f32.bf16.bf16.f32 "
                 "{%0,%1,%2,%3}, {%4,%5,%6,%7}, {%8,%9}, {%0,%1,%2,%3};"
                 : "+f"(c[0]), "+f"(c[1]), "+f"(c[2]), "+f"(c[3])
                 : "r"(a0), "r"(a1), "r"(a2), "r"(a3), "r"(b0), "r"(b1));
}
#define CP16(dst, src) \
    asm volatile("cp.async.cg.shared.global [%0], [%1], 16;" \
                 :: "r"(dst), "l"(src) : "memory")
#define CP_COMMIT() asm volatile("cp.async.commit_group;" ::: "memory")
#define CP_WAIT1()  asm volatile("cp.async.wait_group 1;"  ::: "memory")
#define CP_WAIT0()  asm volatile("cp.async.wait_group 0;"  ::: "memory")

__device__ __forceinline__ uint32_t pack_bf16(float x, float y) {
    __nv_bfloat162 t = __floats2bfloat162_rn(x, y);
    return reinterpret_cast<uint32_t&>(t);
}
__device__ __forceinline__ void split2(float x, float y, uint32_t& hi, uint32_t& lo) {
    __nv_bfloat16 hx = __float2bfloat16(x);
    __nv_bfloat16 hy = __float2bfloat16(y);
    __nv_bfloat162 h; h.x = hx; h.y = hy;
    hi = reinterpret_cast<uint32_t&>(h);
    lo = pack_bf16(x - __bfloat162float(hx), y - __bfloat162float(hy));
}

// ---------------- prep: fp32 -> bf16 hi/lo planes ---------------------------
__global__ __launch_bounds__(256)
void prep_kernel(const float* __restrict__ x,
                 __nv_bfloat16* __restrict__ h,
                 __nv_bfloat16* __restrict__ l, int n4)
{
    const int i = blockIdx.x * 256 + threadIdx.x;
    if (i >= n4) return;
    const float4 v = __ldg((const float4*)x + i);
    uint32_t h0, l0, h1, l1;
    split2(v.x, v.y, h0, l0);
    split2(v.z, v.w, h1, l1);
    ((uint2*)h)[i] = make_uint2(h0, h1);
    ((uint2*)l)[i] = make_uint2(l0, l1);
}

// ===========================================================================
// GEMM: C[M,N] = A[M,K]*W[N,K]^T + bias   (bf16 hi/lo inputs, 3-term mma)
// CTA 128x128, K-tile 64, 3-stage cp.async ring. Rows padded to 144 B.
// ===========================================================================
#define GP_   (128*144)       // plane bytes (18432)
#define GSTG  (4*GP_)         // 73728 per stage
#define GSMEM (3*GSTG)        // 221184
#define GKT   (DM_/64)        // 16

template<bool SPLITO>
__global__ __launch_bounds__(256)
void gemm_bf(const __nv_bfloat16* __restrict__ Ah, const __nv_bfloat16* __restrict__ Al,
             const __nv_bfloat16* __restrict__ Wh, const __nv_bfloat16* __restrict__ Wl,
             const float* __restrict__ bias, float scale,
             float* __restrict__ Cf,
             __nv_bfloat16* __restrict__ Ch, __nv_bfloat16* __restrict__ Cl)
{
    extern __shared__ char smem[];
    const uint32_t sb = smem_u32(smem);
    const int tid = threadIdx.x;
    const int w = tid >> 5, l = tid & 31;
    const int wm = w & 3, wn = w >> 2;
    const int m0 = blockIdx.x * 128;
    const int n0 = blockIdx.y * 128;

    const int srow = tid >> 3;          // 0..31 per 256-chunk slab (row = u>>3)
    const int sch  = tid & 7;

    // stage k-tile kt into ring slot s3
    auto stage = [&](int kt, int s3) {
        const uint32_t buf = sb + (uint32_t)s3 * GSTG;
        const int k0 = kt * 64;
        #pragma unroll
        for (int i = 0; i < 4; i++) {
            const int row = srow + i*32;
            const uint32_t off = (uint32_t)(row*144 + sch*16);
            CP16(buf + 0*GP_ + off, Ah + (size_t)(m0+row)*DM_ + k0 + sch*8);
            CP16(buf + 1*GP_ + off, Al + (size_t)(m0+row)*DM_ + k0 + sch*8);
            CP16(buf + 2*GP_ + off, Wh + (size_t)(n0+row)*DM_ + k0 + sch*8);
            CP16(buf + 3*GP_ + off, Wl + (size_t)(n0+row)*DM_ + k0 + sch*8);
        }
    };

    float acc[2][8][4];
    #pragma unroll
    for (int mt = 0; mt < 2; mt++)
        #pragma unroll
        for (int nt = 0; nt < 8; nt++)
            #pragma unroll
            for (int r = 0; r < 4; r++) acc[mt][nt][r] = 0.f;

    stage(0, 0); CP_COMMIT();
    stage(1, 1); CP_COMMIT();

    const uint32_t a_row = (uint32_t)(wm*32 + (l & 15));
    const uint32_t a_kof = (uint32_t)(8 * (l >> 4));
    const uint32_t b_row = (uint32_t)(wn*64 + (l & 7));
    const uint32_t b_kof = (uint32_t)(8 * ((l >> 3) & 1));

    for (int kt = 0; kt < GKT; kt++) {
        if (kt + 1 < GKT) CP_WAIT1(); else CP_WAIT0();
        __syncthreads();
        if (kt + 2 < GKT) { stage(kt+2, (kt+2)%3); CP_COMMIT(); }

        const uint32_t buf = sb + (uint32_t)(kt % 3) * GSTG;
        #pragma unroll
        for (int ks = 0; ks < 4; ks++) {
            uint32_t ah[2][4], al[2][4];
            #pragma unroll
            for (int mt = 0; mt < 2; mt++) {
                const uint32_t ao = (a_row + mt*16)*144 + (ks*16 + a_kof)*2;
                ldsm_x4(ah[mt][0], ah[mt][1], ah[mt][2], ah[mt][3], buf + 0*GP_ + ao);
                ldsm_x4(al[mt][0], al[mt][1], al[mt][2], al[mt][3], buf + 1*GP_ + ao);
            }
            #pragma unroll
            for (int nt = 0; nt < 8; nt++) {
                const uint32_t bo = (b_row + nt*8)*144 + (ks*16 + b_kof)*2;
                uint32_t bh0, bh1, bl0, bl1;
                ldsm_x2(bh0, bh1, buf + 2*GP_ + bo);
                ldsm_x2(bl0, bl1, buf + 3*GP_ + bo);
                #pragma unroll
                for (int mt = 0; mt < 2; mt++) {
                    mma_bf16(acc[mt][nt], ah[mt][0], ah[mt][1], ah[mt][2], ah[mt][3], bh0, bh1);
                    mma_bf16(acc[mt][nt], ah[mt][0], ah[mt][1], ah[mt][2], ah[mt][3], bl0, bl1);
                    mma_bf16(acc[mt][nt], al[mt][0], al[mt][1], al[mt][2], al[mt][3], bh0, bh1);
                }
            }
        }
        __syncthreads();
    }

    // Epilogue
    #pragma unroll
    for (int mt = 0; mt < 2; mt++) {
        const int mrow = m0 + wm*32 + mt*16 + (l >> 2);
        #pragma unroll
        for (int nt = 0; nt < 8; nt++) {
            const int ncol = n0 + wn*64 + nt*8 + (l & 3)*2;
            const float2 bb = *(const float2*)(bias + ncol);
            float2 o0 = { (acc[mt][nt][0] + bb.x)*scale, (acc[mt][nt][1] + bb.y)*scale };
            float2 o1 = { (acc[mt][nt][2] + bb.x)*scale, (acc[mt][nt][3] + bb.y)*scale };
            if (SPLITO) {
                const int h = ncol >> 6, d = ncol & 63;
                uint32_t hi, lo;
                const int b0i = mrow >> 11, s0i = mrow & (S_-1);
                size_t idx = ((size_t)((b0i*H_ + h)*S_ + s0i))*DK_ + d;
                split2(o0.x, o0.y, hi, lo);
                *(uint32_t*)(Ch + idx) = hi;  *(uint32_t*)(Cl + idx) = lo;
                const int m2 = mrow + 8;
                const int b1i = m2 >> 11, s1i = m2 & (S_-1);
                idx = ((size_t)((b1i*H_ + h)*S_ + s1i))*DK_ + d;
                split2(o1.x, o1.y, hi, lo);
                *(uint32_t*)(Ch + idx) = hi;  *(uint32_t*)(Cl + idx) = lo;
            } else {
                *(float2*)(Cf + (size_t)mrow*DM_ + ncol) = o0;
                *(float2*)(Cf + (size_t)(mrow+8)*DM_ + ncol) = o1;
            }
        }
    }
}

// ===========================================================================
// Flash attention: 128-query tile, 8 warps x 16 rows; K/V from bf16 hi/lo
// planes via cp.async, double-buffered (prefetch next key block).
// ===========================================================================
#define AP_   (64*144)        // plane bytes 9216
#define ASTG  (4*AP_)         // 36864
#define ASMEM (2*ASTG)        // 73728
#define ANB   (S_/64)         // 32 key blocks

__global__ __launch_bounds__(256)
void attn_mma_kernel()
{
    extern __shared__ char smem[];
    const uint32_t sb = smem_u32(smem);
    const int tid = threadIdx.x;
    const int w = tid >> 5, l = tid & 31;
    const int q0 = blockIdx.x * 128;
    const int bh = blockIdx.y;

    const __nv_bfloat16* qph = g_qh + (size_t)bh*S_*DK_;
    const __nv_bfloat16* qpl = g_ql + (size_t)bh*S_*DK_;
    const __nv_bfloat16* kph = g_kh + (size_t)bh*S_*DK_;
    const __nv_bfloat16* kpl = g_kl + (size_t)bh*S_*DK_;
    const __nv_bfloat16* vph = g_vh + (size_t)bh*S_*DK_;
    const __nv_bfloat16* vpl = g_vl + (size_t)bh*S_*DK_;

    const int srow = tid >> 3;   // 0..31
    const int sch  = tid & 7;

    auto stage = [&](int j, int s2) {
        const uint32_t buf = sb + (uint32_t)s2 * ASTG;
        const int r0 = j*64;
        #pragma unroll
        for (int i = 0; i < 2; i++) {
            const int row = srow + i*32;
            const uint32_t off = (uint32_t)(row*144 + sch*16);
            const size_t g = (size_t)(r0+row)*DK_ + sch*8;
            CP16(buf + 0*AP_ + off, kph + g);
            CP16(buf + 1*AP_ + off, kpl + g);
            CP16(buf + 2*AP_ + off, vph + g);
            CP16(buf + 3*AP_ + off, vpl + g);
        }
    };

    stage(0, 0); CP_COMMIT();

    // Q fragments (already scaled in projection)
    uint32_t qh[4][4], ql[4][4];
    {
        const int r1 = q0 + w*16 + (l >> 2);
        #pragma unroll
        for (int ks = 0; ks < 4; ks++) {
            #pragma unroll
            for (int rg = 0; rg < 4; rg++) {
                const int row = r1 + ((rg & 1) ? 8 : 0);
                const int col = ks*16 + (l & 3)*2 + ((rg & 2) ? 8 : 0);
                qh[ks][rg] = *(const uint32_t*)(qph + (size_t)row*DK_ + col);
                ql[ks][rg] = *(const uint32_t*)(qpl + (size_t)row*DK_ + col);
            }
        }
    }

    float o[8][4];
    #pragma unroll
    for (int t = 0; t < 8; t++)
        #pragma unroll
        for (int r = 0; r < 4; r++) o[t][r] = 0.f;
    float m1 = -1e30f, m2 = -1e30f, l1 = 0.f, l2 = 0.f;

    const uint32_t kb_row = (uint32_t)(l & 7);
    const uint32_t kb_kof = (uint32_t)(8 * ((l >> 3) & 1));
    const uint32_t vrow_b = (uint32_t)((l & 7) + 8*((l >> 3) & 1));

    for (int j = 0; j < ANB; j++) {
        CP_WAIT0();
        __syncthreads();
        if (j + 1 < ANB) { stage(j+1, (j+1) & 1); CP_COMMIT(); }

        const uint32_t buf = sb + (uint32_t)(j & 1) * ASTG;

        // S = Q K^T
        float s[8][4];
        #pragma unroll
        for (int t = 0; t < 8; t++)
            #pragma unroll
            for (int r = 0; r < 4; r++) s[t][r] = 0.f;

        #pragma unroll
        for (int ks = 0; ks < 4; ks++) {
            #pragma unroll
            for (int t = 0; t < 8; t++) {
                const uint32_t bo = (t*8 + kb_row)*144 + (ks*16 + kb_kof)*2;
                uint32_t bh0, bh1, bl0, bl1;
                ldsm_x2(bh0, bh1, buf + 0*AP_ + bo);
                ldsm_x2(bl0, bl1, buf + 1*AP_ + bo);
                mma_bf16(s[t], qh[ks][0], qh[ks][1], qh[ks][2], qh[ks][3], bh0, bh1);
                mma_bf16(s[t], qh[ks][0], qh[ks][1], qh[ks][2], qh[ks][3], bl0, bl1);
                mma_bf16(s[t], ql[ks][0], ql[ks][1], ql[ks][2], ql[ks][3], bh0, bh1);
            }
        }

        // Online softmax
        float rm1 = -1e30f, rm2 = -1e30f;
        #pragma unroll
        for (int t = 0; t < 8; t++) {
            rm1 = fmaxf(rm1, fmaxf(s[t][0], s[t][1]));
            rm2 = fmaxf(rm2, fmaxf(s[t][2], s[t][3]));
        }
        rm1 = fmaxf(rm1, __shfl_xor_sync(0xffffffffu, rm1, 1));
        rm1 = fmaxf(rm1, __shfl_xor_sync(0xffffffffu, rm1, 2));
        rm2 = fmaxf(rm2, __shfl_xor_sync(0xffffffffu, rm2, 1));
        rm2 = fmaxf(rm2, __shfl_xor_sync(0xffffffffu, rm2, 2));

        const float mn1 = fmaxf(m1, rm1), mn2 = fmaxf(m2, rm2);
        const float al1 = __expf(m1 - mn1), al2 = __expf(m2 - mn2);
        float sum1 = 0.f, sum2 = 0.f;
        #pragma unroll
        for (int t = 0; t < 8; t++) {
            s[t][0] = __expf(s[t][0] - mn1);
            s[t][1] = __expf(s[t][1] - mn1);
            s[t][2] = __expf(s[t][2] - mn2);
            s[t][3] = __expf(s[t][3] - mn2);
            sum1 += s[t][0] + s[t][1];
            sum2 += s[t][2] + s[t][3];
        }
        sum1 += __shfl_xor_sync(0xffffffffu, sum1, 1);
        sum1 += __shfl_xor_sync(0xffffffffu, sum1, 2);
        sum2 += __shfl_xor_sync(0xffffffffu, sum2, 1);
        sum2 += __shfl_xor_sync(0xffffffffu, sum2, 2);
        l1 = l1*al1 + sum1; l2 = l2*al2 + sum2;
        m1 = mn1; m2 = mn2;
        #pragma unroll
        for (int t = 0; t < 8; t++) {
            o[t][0] *= al1; o[t][1] *= al1;
            o[t][2] *= al2; o[t][3] *= al2;
        }

        // O += P @ V
        #pragma unroll
        for (int ks = 0; ks < 4; ks++) {
            uint32_t ph[4], pl[4];
            split2(s[2*ks  ][0], s[2*ks  ][1], ph[0], pl[0]);
            split2(s[2*ks  ][2], s[2*ks  ][3], ph[1], pl[1]);
            split2(s[2*ks+1][0], s[2*ks+1][1], ph[2], pl[2]);
            split2(s[2*ks+1][2], s[2*ks+1][3], ph[3], pl[3]);
            const uint32_t vrow = (uint32_t)(ks*16) + vrow_b;
            #pragma unroll
            for (int nt = 0; nt < 8; nt++) {
                const uint32_t vo = vrow*144 + (uint32_t)(nt*8)*2;
                uint32_t vh0, vh1, vl0, vl1;
                ldsm_x2t(vh0, vh1, buf + 2*AP_ + vo);
                ldsm_x2t(vl0, vl1, buf + 3*AP_ + vo);
                mma_bf16(o[nt], ph[0], ph[1], ph[2], ph[3], vh0, vh1);
                mma_bf16(o[nt], ph[0], ph[1], ph[2], ph[3], vl0, vl1);
                mma_bf16(o[nt], pl[0], pl[1], pl[2], pl[3], vh0, vh1);
            }
        }
    }

    // Normalize + store ctx as bf16 hi/lo [b, s, h*64+d]
    const float i1 = 1.f / l1, i2 = 1.f / l2;
    const int b = bh >> 4, h = bh & 15;
    const int row1 = q0 + w*16 + (l >> 2);
    #pragma unroll
    for (int t = 0; t < 8; t++) {
        const int col = h*DK_ + t*8 + (l & 3)*2;
        uint32_t hi, lo;
        size_t idx = (size_t)(b*S_ + row1)*DM_ + col;
        split2(o[t][0]*i1, o[t][1]*i1, hi, lo);
        *(uint32_t*)(g_ch + idx) = hi;  *(uint32_t*)(g_cl + idx) = lo;
        idx = (size_t)(b*S_ + row1 + 8)*DM_ + col;
        split2(o[t][2]*i2, o[t][3]*i2, hi, lo);
        *(uint32_t*)(g_ch + idx) = hi;  *(uint32_t*)(g_cl + idx) = lo;
    }
}

// ===========================================================================
extern "C" void kernel_launch(void* const* d_in, const int* in_sizes, int n_in,
                              void* d_out, int out_size)
{
    (void)in_sizes; (void)n_in; (void)out_size;
    const float* query = (const float*)d_in[0];
    const float* key   = (const float*)d_in[1];
    const float* value = (const float*)d_in[2];
    const float* Wq    = (const float*)d_in[3];
    const float* bq    = (const float*)d_in[4];
    const float* Wk    = (const float*)d_in[5];
    const float* bk    = (const float*)d_in[6];
    const float* Wv    = (const float*)d_in[7];
    const float* bv    = (const float*)d_in[8];
    const float* Wo    = (const float*)d_in[9];
    const float* bo    = (const float*)d_in[10];
    float* out = (float*)d_out;

    __nv_bfloat16 *xqh,*xql,*xkh,*xkl,*xvh,*xvl;
    __nv_bfloat16 *wqh,*wql,*wkh,*wkl,*wvh,*wvl,*woh,*wol;
    __nv_bfloat16 *qh,*ql_,*kh,*kl,*vh,*vl,*ch,*cl;
    cudaGetSymbolAddress((void**)&xqh, g_xqh); cudaGetSymbolAddress((void**)&xql, g_xql);
    cudaGetSymbolAddress((void**)&xkh, g_xkh); cudaGetSymbolAddress((void**)&xkl, g_xkl);
    cudaGetSymbolAddress((void**)&xvh, g_xvh); cudaGetSymbolAddress((void**)&xvl, g_xvl);
    cudaGetSymbolAddress((void**)&wqh, g_wqh); cudaGetSymbolAddress((void**)&wql, g_wql);
    cudaGetSymbolAddress((void**)&wkh, g_wkh); cudaGetSymbolAddress((void**)&wkl, g_wkl);
    cudaGetSymbolAddress((void**)&wvh, g_wvh); cudaGetSymbolAddress((void**)&wvl, g_wvl);
    cudaGetSymbolAddress((void**)&woh, g_woh); cudaGetSymbolAddress((void**)&wol, g_wol);
    cudaGetSymbolAddress((void**)&qh, g_qh);   cudaGetSymbolAddress((void**)&ql_, g_ql);
    cudaGetSymbolAddress((void**)&kh, g_kh);   cudaGetSymbolAddress((void**)&kl, g_kl);
    cudaGetSymbolAddress((void**)&vh, g_vh);   cudaGetSymbolAddress((void**)&vl, g_vl);
    cudaGetSymbolAddress((void**)&ch, g_ch);   cudaGetSymbolAddress((void**)&cl, g_cl);

    cudaFuncSetAttribute(gemm_bf<true>,
                         cudaFuncAttributeMaxDynamicSharedMemorySize, GSMEM);
    cudaFuncSetAttribute(gemm_bf<false>,
                         cudaFuncAttributeMaxDynamicSharedMemorySize, GSMEM);
    cudaFuncSetAttribute(attn_mma_kernel,
                         cudaFuncAttributeMaxDynamicSharedMemorySize, ASMEM);

    // prep: inputs (2M float4 each) + weights (256K float4 each)
    const int nA4 = (int)(NA_/4), nW4 = (int)(NW_/4);
    prep_kernel<<<(nA4+255)/256, 256>>>(query, xqh, xql, nA4);
    prep_kernel<<<(nA4+255)/256, 256>>>(key,   xkh, xkl, nA4);
    prep_kernel<<<(nA4+255)/256, 256>>>(value, xvh, xvl, nA4);
    prep_kernel<<<(nW4+255)/256, 256>>>(Wq, wqh, wql, nW4);
    prep_kernel<<<(nW4+255)/256, 256>>>(Wk, wkh, wkl, nW4);
    prep_kernel<<<(nW4+255)/256, 256>>>(Wv, wvh, wvl, nW4);
    prep_kernel<<<(nW4+255)/256, 256>>>(Wo, woh, wol, nW4);

    const dim3 gproj(M_/128, DM_/128);   // 64 x 8
    gemm_bf<true><<<gproj, 256, GSMEM>>>(xqh, xql, wqh, wql, bq, 0.125f,
                                         nullptr, qh, ql_);
    gemm_bf<true><<<gproj, 256, GSMEM>>>(xkh, xkl, wkh, wkl, bk, 1.0f,
                                         nullptr, kh, kl);
    gemm_bf<true><<<gproj, 256, GSMEM>>>(xvh, xvl, wvh, wvl, bv, 1.0f,
                                         nullptr, vh, vl);

    attn_mma_kernel<<<dim3(S_/128, B_*H_), 256, ASMEM>>>();

    gemm_bf<false><<<gproj, 256, GSMEM>>>(ch, cl, woh, wol, bo, 1.0f,
                                          out, nullptr, nullptr);
}

// round 8
// speedup vs baseline: 2.9674x; 1.0448x over previous
#include <cuda_runtime.h>
#include <cuda_bf16.h>
#include <cstdint>

#define B_   4
#define S_   2048
#define H_   16
#define DK_  64
#define DM_  1024
#define M_   (B_*S_)          // 8192
#define NA_  ((size_t)M_*DM_) // 8M elems
#define NW_  ((size_t)DM_*DM_)// 1M elems

// ---------------- scratch (__device__ globals; no allocs) ------------------
__device__ __nv_bfloat16 g_xqh[NA_], g_xql[NA_];
__device__ __nv_bfloat16 g_xkh[NA_], g_xkl[NA_];
__device__ __nv_bfloat16 g_xvh[NA_], g_xvl[NA_];
__device__ __nv_bfloat16 g_wqh[NW_], g_wql[NW_];
__device__ __nv_bfloat16 g_wkh[NW_], g_wkl[NW_];
__device__ __nv_bfloat16 g_wvh[NW_], g_wvl[NW_];
__device__ __nv_bfloat16 g_woh[NW_], g_wol[NW_];
__device__ __nv_bfloat16 g_qh[NA_], g_ql[NA_];
__device__ __nv_bfloat16 g_kh[NA_], g_kl[NA_];
__device__ __nv_bfloat16 g_vh[NA_], g_vl[NA_];
__device__ __nv_bfloat16 g_ch[NA_], g_cl[NA_];

// ---------------- PTX helpers ----------------------------------------------
__device__ __forceinline__ uint32_t smem_u32(const void* p) {
    uint32_t a;
    asm("{ .reg .u64 t; cvta.to.shared.u64 t, %1; cvt.u32.u64 %0, t; }"
        : "=r"(a) : "l"(p));
    return a;
}
__device__ __forceinline__ void ldsm_x4(uint32_t& r0, uint32_t& r1,
                                        uint32_t& r2, uint32_t& r3, uint32_t a) {
    asm volatile("ldmatrix.sync.aligned.m8n8.x4.shared.b16 {%0,%1,%2,%3}, [%4];"
                 : "=r"(r0), "=r"(r1), "=r"(r2), "=r"(r3) : "r"(a));
}
__device__ __forceinline__ void ldsm_x4t(uint32_t& r0, uint32_t& r1,
                                         uint32_t& r2, uint32_t& r3, uint32_t a) {
    asm volatile("ldmatrix.sync.aligned.m8n8.x4.trans.shared.b16 {%0,%1,%2,%3}, [%4];"
                 : "=r"(r0), "=r"(r1), "=r"(r2), "=r"(r3) : "r"(a));
}
__device__ __forceinline__ void mma_bf16(float* c,
                                         uint32_t a0, uint32_t a1, uint32_t a2, uint32_t a3,
                                         uint32_t b0, uint32_t b1) {
    asm volatile("mma.sync.aligned.m16n8k16.row.col.f32.bf16.bf16.f32 "
                 "{%0,%1,%2,%3}, {%4,%5,%6,%7}, {%8,%9}, {%0,%1,%2,%3};"
                 : "+f"(c[0]), "+f"(c[1]), "+f"(c[2]), "+f"(c[3])
                 : "r"(a0), "r"(a1), "r"(a2), "r"(a3), "r"(b0), "r"(b1));
}
#define CP16(dst, src) \
    asm volatile("cp.async.cg.shared.global [%0], [%1], 16;" \
                 :: "r"(dst), "l"(src) : "memory")
#define CP_COMMIT() asm volatile("cp.async.commit_group;" ::: "memory")
#define CP_WAIT0()  asm volatile("cp.async.wait_group 0;"  ::: "memory")

__device__ __forceinline__ uint32_t pack_bf16(float x, float y) {
    __nv_bfloat162 t = __floats2bfloat162_rn(x, y);
    return reinterpret_cast<uint32_t&>(t);
}
__device__ __forceinline__ void split2(float x, float y, uint32_t& hi, uint32_t& lo) {
    __nv_bfloat16 hx = __float2bfloat16(x);
    __nv_bfloat16 hy = __float2bfloat16(y);
    __nv_bfloat162 h; h.x = hx; h.y = hy;
    hi = reinterpret_cast<uint32_t&>(h);
    lo = pack_bf16(x - __bfloat162float(hx), y - __bfloat162float(hy));
}

// ---------------- prep: fp32 -> bf16 hi/lo planes (batched) -----------------
struct Prep3 { const float* x[3]; __nv_bfloat16* h[3]; __nv_bfloat16* l[3]; int n4; };

__global__ __launch_bounds__(256)
void prep_batch(Prep3 pa)
{
    const int z = blockIdx.y;
    const int i = blockIdx.x * 256 + threadIdx.x;
    if (i >= pa.n4) return;
    const float4 v = __ldg((const float4*)pa.x[z] + i);
    uint32_t h0, l0, h1, l1;
    split2(v.x, v.y, h0, l0);
    split2(v.z, v.w, h1, l1);
    ((uint2*)pa.h[z])[i] = make_uint2(h0, h1);
    ((uint2*)pa.l[z])[i] = make_uint2(l0, l1);
}

// ===========================================================================
// GEMM: C[M,N] = A[M,K]*W[N,K]^T + bias   (bf16 hi/lo, 3-term mma)
// CTA 128x128, K-tile 32, 2-stage cp.async double buffer.
// Rows padded to 80 B (16B-aligned, LDSM conflict-free) -> 80 KB smem,
// 2 CTAs/SM. Batched over gridDim.z via GemmArgs3.
// ===========================================================================
#define GP2    (128*80)        // plane bytes 10240
#define GSTG2  (4*GP2)         // 40960
#define GSMEM2 (2*GSTG2)       // 81920
#define GKT2   (DM_/32)        // 32

struct GemmArgs {
    const __nv_bfloat16 *Ah, *Al, *Wh, *Wl;
    const float* bias;
    float scale;
    float* Cf;
    __nv_bfloat16 *Ch, *Cl;
};
struct GemmArgs3 { GemmArgs g[3]; };

template<bool SPLITO>
__global__ __launch_bounds__(256, 2)
void gemm_bf(GemmArgs3 aa)
{
    const GemmArgs ga = aa.g[blockIdx.z];
    extern __shared__ char smem[];
    const uint32_t sb = smem_u32(smem);
    const int tid = threadIdx.x;
    const int w = tid >> 5, l = tid & 31;
    const int wm = w & 3, wn = w >> 2;
    const int m0 = blockIdx.x * 128;
    const int n0 = blockIdx.y * 128;

    const int srow = tid >> 2;          // 0..63
    const int sch  = tid & 3;           // 4 x 16B = 64B data per 32-elem row

    auto stage = [&](int kt, int s2) {
        const uint32_t buf = sb + (uint32_t)s2 * GSTG2;
        const int k0 = kt * 32;
        #pragma unroll
        for (int i = 0; i < 2; i++) {
            const int row = srow + i*64;
            const uint32_t off = (uint32_t)(row*80 + sch*16);
            CP16(buf + 0*GP2 + off, ga.Ah + (size_t)(m0+row)*DM_ + k0 + sch*8);
            CP16(buf + 1*GP2 + off, ga.Al + (size_t)(m0+row)*DM_ + k0 + sch*8);
            CP16(buf + 2*GP2 + off, ga.Wh + (size_t)(n0+row)*DM_ + k0 + sch*8);
            CP16(buf + 3*GP2 + off, ga.Wl + (size_t)(n0+row)*DM_ + k0 + sch*8);
        }
    };

    float acc[2][8][4];
    #pragma unroll
    for (int mt = 0; mt < 2; mt++)
        #pragma unroll
        for (int nt = 0; nt < 8; nt++)
            #pragma unroll
            for (int r = 0; r < 4; r++) acc[mt][nt][r] = 0.f;

    stage(0, 0); CP_COMMIT();

    const uint32_t a_row = (uint32_t)(wm*32 + (l & 15));
    const uint32_t a_kof = (uint32_t)(8 * (l >> 4));
    const uint32_t b4row = (uint32_t)(wn*64 + ((l >> 4) & 1)*8 + (l & 7));
    const uint32_t b_kof = (uint32_t)(8 * ((l >> 3) & 1));

    for (int kt = 0; kt < GKT2; kt++) {
        CP_WAIT0();
        __syncthreads();
        if (kt + 1 < GKT2) { stage(kt+1, (kt+1) & 1); CP_COMMIT(); }

        const uint32_t buf = sb + (uint32_t)((kt & 1) * GSTG2);
        #pragma unroll
        for (int ks = 0; ks < 2; ks++) {
            uint32_t ah[2][4], al[2][4];
            #pragma unroll
            for (int mt = 0; mt < 2; mt++) {
                const uint32_t ao = (a_row + mt*16)*80 + (ks*16 + a_kof)*2;
                ldsm_x4(ah[mt][0], ah[mt][1], ah[mt][2], ah[mt][3], buf + 0*GP2 + ao);
                ldsm_x4(al[mt][0], al[mt][1], al[mt][2], al[mt][3], buf + 1*GP2 + ao);
            }
            #pragma unroll
            for (int np = 0; np < 4; np++) {
                const uint32_t bo = (b4row + np*16)*80 + (ks*16 + b_kof)*2;
                uint32_t h0,h1,h2,h3, l0,l1,l2,l3;
                ldsm_x4(h0, h1, h2, h3, buf + 2*GP2 + bo);
                ldsm_x4(l0, l1, l2, l3, buf + 3*GP2 + bo);
                #pragma unroll
                for (int mt = 0; mt < 2; mt++) {
                    mma_bf16(acc[mt][2*np  ], ah[mt][0], ah[mt][1], ah[mt][2], ah[mt][3], h0, h1);
                    mma_bf16(acc[mt][2*np  ], ah[mt][0], ah[mt][1], ah[mt][2], ah[mt][3], l0, l1);
                    mma_bf16(acc[mt][2*np  ], al[mt][0], al[mt][1], al[mt][2], al[mt][3], h0, h1);
                    mma_bf16(acc[mt][2*np+1], ah[mt][0], ah[mt][1], ah[mt][2], ah[mt][3], h2, h3);
                    mma_bf16(acc[mt][2*np+1], ah[mt][0], ah[mt][1], ah[mt][2], ah[mt][3], l2, l3);
                    mma_bf16(acc[mt][2*np+1], al[mt][0], al[mt][1], al[mt][2], al[mt][3], h2, h3);
                }
            }
        }
    }

    // Epilogue
    #pragma unroll
    for (int mt = 0; mt < 2; mt++) {
        const int mrow = m0 + wm*32 + mt*16 + (l >> 2);
        #pragma unroll
        for (int nt = 0; nt < 8; nt++) {
            const int ncol = n0 + wn*64 + nt*8 + (l & 3)*2;
            const float2 bb = *(const float2*)(ga.bias + ncol);
            float2 o0 = { (acc[mt][nt][0] + bb.x)*ga.scale, (acc[mt][nt][1] + bb.y)*ga.scale };
            float2 o1 = { (acc[mt][nt][2] + bb.x)*ga.scale, (acc[mt][nt][3] + bb.y)*ga.scale };
            if (SPLITO) {
                const int h = ncol >> 6, d = ncol & 63;
                uint32_t hi, lo;
                const int b0i = mrow >> 11, s0i = mrow & (S_-1);
                size_t idx = ((size_t)((b0i*H_ + h)*S_ + s0i))*DK_ + d;
                split2(o0.x, o0.y, hi, lo);
                *(uint32_t*)(ga.Ch + idx) = hi;  *(uint32_t*)(ga.Cl + idx) = lo;
                const int m2 = mrow + 8;
                const int b1i = m2 >> 11, s1i = m2 & (S_-1);
                idx = ((size_t)((b1i*H_ + h)*S_ + s1i))*DK_ + d;
                split2(o1.x, o1.y, hi, lo);
                *(uint32_t*)(ga.Ch + idx) = hi;  *(uint32_t*)(ga.Cl + idx) = lo;
            } else {
                *(float2*)(ga.Cf + (size_t)mrow*DM_ + ncol) = o0;
                *(float2*)(ga.Cf + (size_t)(mrow+8)*DM_ + ncol) = o1;
            }
        }
    }
}

// ===========================================================================
// Flash attention: 64-query CTA, 8 warps (4m x 2n). wn splits the 64 keys:
// each warp scores 32 keys + accumulates its key-half of O (summed at end).
// Softmax max/sum exchanged between partner warps (w ^ 4) via smem.
// 2 CTAs/SM (regs<=128, smem 73 KB).
// ===========================================================================
#define AP_   (64*144)        // plane bytes 9216 (144 % 16 == 0)
#define ASTG  (4*AP_)         // 36864
#define ASMEM (2*ASTG + 1024) // 74752
#define ANB   (S_/64)         // 32 key blocks
#define RM_F  (2*ASTG/4)      // float index of max-exchange buffer
#define RS_F  (RM_F + 128)

__global__ __launch_bounds__(256, 2)
void attn_mma_kernel()
{
    extern __shared__ char smem[];
    const uint32_t sb = smem_u32(smem);
    float* smf = (float*)smem;
    const int tid = threadIdx.x;
    const int w = tid >> 5, l = tid & 31;
    const int wm = w & 3, wn = w >> 2;
    const int q0 = blockIdx.x * 64;
    const int bh = blockIdx.y;

    const __nv_bfloat16* qph = g_qh + (size_t)bh*S_*DK_;
    const __nv_bfloat16* qpl = g_ql + (size_t)bh*S_*DK_;
    const __nv_bfloat16* kph = g_kh + (size_t)bh*S_*DK_;
    const __nv_bfloat16* kpl = g_kl + (size_t)bh*S_*DK_;
    const __nv_bfloat16* vph = g_vh + (size_t)bh*S_*DK_;
    const __nv_bfloat16* vpl = g_vl + (size_t)bh*S_*DK_;

    const int srow = tid >> 3;   // 0..31
    const int sch  = tid & 7;

    auto stage = [&](int j, int s2) {
        const uint32_t buf = sb + (uint32_t)s2 * ASTG;
        const int r0 = j*64;
        #pragma unroll
        for (int i = 0; i < 2; i++) {
            const int row = srow + i*32;
            const uint32_t off = (uint32_t)(row*144 + sch*16);
            const size_t g = (size_t)(r0+row)*DK_ + sch*8;
            CP16(buf + 0*AP_ + off, kph + g);
            CP16(buf + 1*AP_ + off, kpl + g);
            CP16(buf + 2*AP_ + off, vph + g);
            CP16(buf + 3*AP_ + off, vpl + g);
        }
    };

    stage(0, 0); CP_COMMIT();

    // Q fragments (pre-scaled in projection); duplicated across wn pair
    uint32_t qh[4][4], ql[4][4];
    {
        const int r1 = q0 + wm*16 + (l >> 2);
        #pragma unroll
        for (int ks = 0; ks < 4; ks++) {
            #pragma unroll
            for (int rg = 0; rg < 4; rg++) {
                const int row = r1 + ((rg & 1) ? 8 : 0);
                const int col = ks*16 + (l & 3)*2 + ((rg & 2) ? 8 : 0);
                qh[ks][rg] = *(const uint32_t*)(qph + (size_t)row*DK_ + col);
                ql[ks][rg] = *(const uint32_t*)(qpl + (size_t)row*DK_ + col);
            }
        }
    }

    float o[8][4];
    #pragma unroll
    for (int t = 0; t < 8; t++)
        #pragma unroll
        for (int r = 0; r < 4; r++) o[t][r] = 0.f;
    float m1 = -1e30f, m2 = -1e30f, l1 = 0.f, l2 = 0.f;

    const uint32_t kqrow = (uint32_t)(wn*32 + ((l >> 4) & 1)*8 + (l & 7));
    const uint32_t kb_kof = (uint32_t)(8 * ((l >> 3) & 1));
    const uint32_t vrow_b = (uint32_t)(((l >> 3) & 1)*8 + (l & 7));
    const uint32_t vcol_b = (uint32_t)(((l >> 4) & 1)*8);
    const int pw = w ^ 4;             // partner warp (other key half)
    const int rq = l >> 2;            // row quad index 0..7

    for (int j = 0; j < ANB; j++) {
        CP_WAIT0();
        __syncthreads();
        if (j + 1 < ANB) { stage(j+1, (j+1) & 1); CP_COMMIT(); }

        const uint32_t buf = sb + (uint32_t)(j & 1) * ASTG;

        // S = Q K^T over this warp's 32 keys (4 n-tiles)
        float s[4][4];
        #pragma unroll
        for (int t = 0; t < 4; t++)
            #pragma unroll
            for (int r = 0; r < 4; r++) s[t][r] = 0.f;

        #pragma unroll
        for (int ks = 0; ks < 4; ks++) {
            #pragma unroll
            for (int tp = 0; tp < 2; tp++) {
                const uint32_t bo = (kqrow + tp*16)*144 + (ks*16 + kb_kof)*2;
                uint32_t h0,h1,h2,h3, l0,l1_,l2,l3;
                ldsm_x4(h0, h1, h2, h3, buf + 0*AP_ + bo);
                ldsm_x4(l0, l1_, l2, l3, buf + 1*AP_ + bo);
                mma_bf16(s[2*tp  ], qh[ks][0], qh[ks][1], qh[ks][2], qh[ks][3], h0, h1);
                mma_bf16(s[2*tp  ], qh[ks][0], qh[ks][1], qh[ks][2], qh[ks][3], l0, l1_);
                mma_bf16(s[2*tp  ], ql[ks][0], ql[ks][1], ql[ks][2], ql[ks][3], h0, h1);
                mma_bf16(s[2*tp+1], qh[ks][0], qh[ks][1], qh[ks][2], qh[ks][3], h2, h3);
                mma_bf16(s[2*tp+1], qh[ks][0], qh[ks][1], qh[ks][2], qh[ks][3], l2, l3);
                mma_bf16(s[2*tp+1], ql[ks][0], ql[ks][1], ql[ks][2], ql[ks][3], h2, h3);
            }
        }

        // local row max over this warp's 32 keys
        float rm1 = -1e30f, rm2 = -1e30f;
        #pragma unroll
        for (int t = 0; t < 4; t++) {
            rm1 = fmaxf(rm1, fmaxf(s[t][0], s[t][1]));
            rm2 = fmaxf(rm2, fmaxf(s[t][2], s[t][3]));
        }
        rm1 = fmaxf(rm1, __shfl_xor_sync(0xffffffffu, rm1, 1));
        rm1 = fmaxf(rm1, __shfl_xor_sync(0xffffffffu, rm1, 2));
        rm2 = fmaxf(rm2, __shfl_xor_sync(0xffffffffu, rm2, 1));
        rm2 = fmaxf(rm2, __shfl_xor_sync(0xffffffffu, rm2, 2));

        // exchange with partner warp -> global row max over 64 keys
        if ((l & 3) == 0) {
            smf[RM_F + w*16 + rq]     = rm1;
            smf[RM_F + w*16 + 8 + rq] = rm2;
        }
        __syncthreads();
        rm1 = fmaxf(rm1, smf[RM_F + pw*16 + rq]);
        rm2 = fmaxf(rm2, smf[RM_F + pw*16 + 8 + rq]);

        const float mn1 = fmaxf(m1, rm1), mn2 = fmaxf(m2, rm2);
        const float al1 = __expf(m1 - mn1), al2 = __expf(m2 - mn2);
        float sum1 = 0.f, sum2 = 0.f;
        #pragma unroll
        for (int t = 0; t < 4; t++) {
            s[t][0] = __expf(s[t][0] - mn1);
            s[t][1] = __expf(s[t][1] - mn1);
            s[t][2] = __expf(s[t][2] - mn2);
            s[t][3] = __expf(s[t][3] - mn2);
            sum1 += s[t][0] + s[t][1];
            sum2 += s[t][2] + s[t][3];
        }
        sum1 += __shfl_xor_sync(0xffffffffu, sum1, 1);
        sum1 += __shfl_xor_sync(0xffffffffu, sum1, 2);
        sum2 += __shfl_xor_sync(0xffffffffu, sum2, 1);
        sum2 += __shfl_xor_sync(0xffffffffu, sum2, 2);
        if ((l & 3) == 0) {
            smf[RS_F + w*16 + rq]     = sum1;
            smf[RS_F + w*16 + 8 + rq] = sum2;
        }
        __syncthreads();
        sum1 += smf[RS_F + pw*16 + rq];
        sum2 += smf[RS_F + pw*16 + 8 + rq];

        l1 = l1*al1 + sum1; l2 = l2*al2 + sum2;
        m1 = mn1; m2 = mn2;
        #pragma unroll
        for (int t = 0; t < 8; t++) {
            o[t][0] *= al1; o[t][1] *= al1;
            o[t][2] *= al2; o[t][3] *= al2;
        }

        // O += P @ V over this warp's keys (2 k16 steps)
        #pragma unroll
        for (int kss = 0; kss < 2; kss++) {
            const int ks_g = wn*2 + kss;
            uint32_t ph[4], pl[4];
            split2(s[2*kss  ][0], s[2*kss  ][1], ph[0], pl[0]);
            split2(s[2*kss  ][2], s[2*kss  ][3], ph[1], pl[1]);
            split2(s[2*kss+1][0], s[2*kss+1][1], ph[2], pl[2]);
            split2(s[2*kss+1][2], s[2*kss+1][3], ph[3], pl[3]);
            const uint32_t vrow = (uint32_t)(ks_g*16) + vrow_b;
            #pragma unroll
            for (int np = 0; np < 4; np++) {
                const uint32_t vo = vrow*144 + (np*16 + vcol_b)*2;
                uint32_t h0,h1,h2,h3, l0,l1_,l2,l3;
                ldsm_x4t(h0, h1, h2, h3, buf + 2*AP_ + vo);
                ldsm_x4t(l0, l1_, l2, l3, buf + 3*AP_ + vo);
                mma_bf16(o[2*np  ], ph[0], ph[1], ph[2], ph[3], h0, h1);
                mma_bf16(o[2*np  ], ph[0], ph[1], ph[2], ph[3], l0, l1_);
                mma_bf16(o[2*np  ], pl[0], pl[1], pl[2], pl[3], h0, h1);
                mma_bf16(o[2*np+1], ph[0], ph[1], ph[2], ph[3], h2, h3);
                mma_bf16(o[2*np+1], ph[0], ph[1], ph[2], ph[3], l2, l3);
                mma_bf16(o[2*np+1], pl[0], pl[1], pl[2], pl[3], h2, h3);
            }
        }
    }

    // Combine the two key-half O partials (wn=1 -> smem -> wn=0 adds)
    __syncthreads();
    float* comb = (float*)smem;         // 64 rows x 66 floats (padded)
    const int rl  = wm*16 + (l >> 2);
    const int cl2 = (l & 3)*2;
    if (wn == 1) {
        #pragma unroll
        for (int t = 0; t < 8; t++) {
            *(float2*)&comb[ rl     *66 + t*8 + cl2] = make_float2(o[t][0], o[t][1]);
            *(float2*)&comb[(rl + 8)*66 + t*8 + cl2] = make_float2(o[t][2], o[t][3]);
        }
    }
    __syncthreads();
    if (wn == 0) {
        const float i1 = 1.f / l1, i2 = 1.f / l2;
        const int b = bh >> 4, h = bh & 15;
        const int row1 = q0 + rl;
        #pragma unroll
        for (int t = 0; t < 8; t++) {
            const float2 p0 = *(const float2*)&comb[ rl     *66 + t*8 + cl2];
            const float2 p1 = *(const float2*)&comb[(rl + 8)*66 + t*8 + cl2];
            const int col = h*DK_ + t*8 + cl2;
            uint32_t hi, lo;
            size_t idx = (size_t)(b*S_ + row1)*DM_ + col;
            split2((o[t][0] + p0.x)*i1, (o[t][1] + p0.y)*i1, hi, lo);
            *(uint32_t*)(g_ch + idx) = hi;  *(uint32_t*)(g_cl + idx) = lo;
            idx = (size_t)(b*S_ + row1 + 8)*DM_ + col;
            split2((o[t][2] + p1.x)*i2, (o[t][3] + p1.y)*i2, hi, lo);
            *(uint32_t*)(g_ch + idx) = hi;  *(uint32_t*)(g_cl + idx) = lo;
        }
    }
}

// ===========================================================================
extern "C" void kernel_launch(void* const* d_in, const int* in_sizes, int n_in,
                              void* d_out, int out_size)
{
    (void)in_sizes; (void)n_in; (void)out_size;
    const float* query = (const float*)d_in[0];
    const float* key   = (const float*)d_in[1];
    const float* value = (const float*)d_in[2];
    const float* Wq    = (const float*)d_in[3];
    const float* bq    = (const float*)d_in[4];
    const float* Wk    = (const float*)d_in[5];
    const float* bk    = (const float*)d_in[6];
    const float* Wv    = (const float*)d_in[7];
    const float* bv    = (const float*)d_in[8];
    const float* Wo    = (const float*)d_in[9];
    const float* bo    = (const float*)d_in[10];
    float* out = (float*)d_out;

    __nv_bfloat16 *xqh,*xql,*xkh,*xkl,*xvh,*xvl;
    __nv_bfloat16 *wqh,*wql,*wkh,*wkl,*wvh,*wvl,*woh,*wol;
    __nv_bfloat16 *qh,*ql_,*kh,*kl,*vh,*vl,*ch,*cl;
    cudaGetSymbolAddress((void**)&xqh, g_xqh); cudaGetSymbolAddress((void**)&xql, g_xql);
    cudaGetSymbolAddress((void**)&xkh, g_xkh); cudaGetSymbolAddress((void**)&xkl, g_xkl);
    cudaGetSymbolAddress((void**)&xvh, g_xvh); cudaGetSymbolAddress((void**)&xvl, g_xvl);
    cudaGetSymbolAddress((void**)&wqh, g_wqh); cudaGetSymbolAddress((void**)&wql, g_wql);
    cudaGetSymbolAddress((void**)&wkh, g_wkh); cudaGetSymbolAddress((void**)&wkl, g_wkl);
    cudaGetSymbolAddress((void**)&wvh, g_wvh); cudaGetSymbolAddress((void**)&wvl, g_wvl);
    cudaGetSymbolAddress((void**)&woh, g_woh); cudaGetSymbolAddress((void**)&wol, g_wol);
    cudaGetSymbolAddress((void**)&qh, g_qh);   cudaGetSymbolAddress((void**)&ql_, g_ql);
    cudaGetSymbolAddress((void**)&kh, g_kh);   cudaGetSymbolAddress((void**)&kl, g_kl);
    cudaGetSymbolAddress((void**)&vh, g_vh);   cudaGetSymbolAddress((void**)&vl, g_vl);
    cudaGetSymbolAddress((void**)&ch, g_ch);   cudaGetSymbolAddress((void**)&cl, g_cl);

    cudaFuncSetAttribute(gemm_bf<true>,
                         cudaFuncAttributeMaxDynamicSharedMemorySize, GSMEM2);
    cudaFuncSetAttribute(gemm_bf<false>,
                         cudaFuncAttributeMaxDynamicSharedMemorySize, GSMEM2);
    cudaFuncSetAttribute(attn_mma_kernel,
                         cudaFuncAttributeMaxDynamicSharedMemorySize, ASMEM);

    const int nA4 = (int)(NA_/4), nW4 = (int)(NW_/4);

    Prep3 pi; pi.n4 = nA4;
    pi.x[0]=query; pi.h[0]=xqh; pi.l[0]=xql;
    pi.x[1]=key;   pi.h[1]=xkh; pi.l[1]=xkl;
    pi.x[2]=value; pi.h[2]=xvh; pi.l[2]=xvl;
    prep_batch<<<dim3((nA4+255)/256, 3), 256>>>(pi);

    Prep3 pw1; pw1.n4 = nW4;
    pw1.x[0]=Wq; pw1.h[0]=wqh; pw1.l[0]=wql;
    pw1.x[1]=Wk; pw1.h[1]=wkh; pw1.l[1]=wkl;
    pw1.x[2]=Wv; pw1.h[2]=wvh; pw1.l[2]=wvl;
    prep_batch<<<dim3((nW4+255)/256, 3), 256>>>(pw1);
    Prep3 pw2; pw2.n4 = nW4;
    pw2.x[0]=Wo; pw2.h[0]=woh; pw2.l[0]=wol;
    pw2.x[1]=Wo; pw2.h[1]=woh; pw2.l[1]=wol;
    pw2.x[2]=Wo; pw2.h[2]=woh; pw2.l[2]=wol;
    prep_batch<<<dim3((nW4+255)/256, 1), 256>>>(pw2);

    GemmArgs3 gq;
    gq.g[0] = { xqh, xql, wqh, wql, bq, 0.125f, nullptr, qh,  ql_ };
    gq.g[1] = { xkh, xkl, wkh, wkl, bk, 1.0f,   nullptr, kh,  kl  };
    gq.g[2] = { xvh, xvl, wvh, wvl, bv, 1.0f,   nullptr, vh,  vl  };
    gemm_bf<true><<<dim3(M_/128, DM_/128, 3), 256, GSMEM2>>>(gq);

    attn_mma_kernel<<<dim3(S_/64, B_*H_), 256, ASMEM>>>();

    GemmArgs3 go;
    go.g[0] = { ch, cl, woh, wol, bo, 1.0f, out, nullptr, nullptr };
    go.g[1] = go.g[0];
    go.g[2] = go.g[0];
    gemm_bf<false><<<dim3(M_/128, DM_/128, 1), 256, GSMEM2>>>(go);
}